// round 12
// baseline (speedup 1.0000x reference)
#include <cuda_runtime.h>
#include <cuda_fp16.h>
#include <math.h>
#include <stdint.h>

#define BB 16
#define CC 512
#define NN 2304
#define NT 18            // NN / 128 tiles
#define NPAIRS 171       // NT*(NT+1)/2

// ---------------- scratch (__device__ globals; no allocs allowed) -----------
__device__ __half g_xn[(size_t)BB * CC * NN];   // fp16-RN normalized x, [b][c][n]
__device__ float g_att[BB * NN];
__device__ float g_refine[BB * NN];

__device__ __forceinline__ uint32_t smem_u32(const void* p) {
    uint32_t a;
    asm("{ .reg .u64 t; cvta.to.shared.u64 t, %1; cvt.u32.u64 %0, t; }" : "=r"(a) : "l"(p));
    return a;
}
__device__ __forceinline__ void cp_async16(uint32_t dst, const void* src) {
    asm volatile("cp.async.cg.shared.global [%0], [%1], 16;" :: "r"(dst), "l"(src) : "memory");
}
#define CP_COMMIT() asm volatile("cp.async.commit_group;" ::: "memory")

__device__ __forceinline__ void mma_f16(float c[4], const uint32_t a[4], const uint32_t b[2]) {
    asm("mma.sync.aligned.m16n8k16.row.col.f32.f16.f16.f32 "
        "{%0,%1,%2,%3}, {%4,%5,%6,%7}, {%8,%9}, {%0,%1,%2,%3};"
        : "+f"(c[0]), "+f"(c[1]), "+f"(c[2]), "+f"(c[3])
        : "r"(a[0]), "r"(a[1]), "r"(a[2]), "r"(a[3]), "r"(b[0]), "r"(b[1]));
}

#define LDSM_X4_T(r0, r1, r2, r3, addr) \
    asm volatile("ldmatrix.sync.aligned.m8n8.x4.trans.shared.b16 {%0,%1,%2,%3}, [%4];" \
        : "=r"(r0), "=r"(r1), "=r"(r2), "=r"(r3) : "r"(addr))

// ---------------------------------------------------------------------------
// prep: block = 32 n x 8 c-slices (64 c each). Phase1 ss/dot -> inv, att;
// phase2 cache-hot re-read writes g_xn fp16. grid = BB * NN/32 = 1152
// ---------------------------------------------------------------------------
__global__ void __launch_bounds__(256) prep_kernel(const float* __restrict__ x,
                                                   const float* __restrict__ wq) {
    __shared__ float swq[CC];
    __shared__ float s_ss[256], s_dot[256];
    __shared__ float s_inv[32];

    int tid = threadIdx.x;
    for (int i = tid; i < CC; i += 256) swq[i] = wq[i];
    __syncthreads();

    int b  = blockIdx.x / (NN / 32);
    int nt = blockIdx.x % (NN / 32);
    int cs = tid >> 5;          // c-slice 0..7 (64 c each)
    int nl = tid & 31;
    int n  = nt * 32 + nl;

    const float* xb = x + ((size_t)b * CC + cs * 64) * NN + n;
    const float* wp = swq + cs * 64;

    float ss = 0.f, dot = 0.f;
    #pragma unroll 16
    for (int c = 0; c < 64; c++) {
        float v = xb[(size_t)c * NN];
        ss  = fmaf(v, v, ss);
        dot = fmaf(v, wp[c], dot);
    }
    s_ss[tid] = ss; s_dot[tid] = dot;
    __syncthreads();

    if (tid < 32) {
        float tss = 0.f, td = 0.f;
        #pragma unroll
        for (int k = 0; k < 8; k++) {
            tss += s_ss[tid + 32 * k];
            td  += s_dot[tid + 32 * k];
        }
        s_inv[tid] = 1.0f / fmaxf(sqrtf(tss), 1e-12f);
        int gid = b * NN + nt * 32 + tid;
        g_att[gid]    = (td > 20.0f) ? td : log1pf(expf(td));
        g_refine[gid] = 0.0f;
    }
    __syncthreads();

    float inv = s_inv[nl];
    __half* ob = g_xn + ((size_t)b * CC + cs * 64) * NN + n;
    #pragma unroll 16
    for (int c = 0; c < 64; c++) {
        float v = xb[(size_t)c * NN];
        ob[(size_t)c * NN] = __float2half_rn(v * inv);
    }
}

// ---------------------------------------------------------------------------
// gemm: per (b, tile-pair i<=j): S = Xn_i^T Xn_j over K=512 (fp16 mma.sync)
// 128x128 CTA tile, 4 warps of 64x64 (0.125 B/MAC fragment traffic).
// smem tiles [k][n], row stride 136 halves; ldmatrix.x4.trans fragments.
// BK=64, 3-stage cp.async pipeline, one __syncthreads per round.
// ---------------------------------------------------------------------------
#define BK 64
#define ROWH 136                         // halves per smem row (128 + 8 pad)
#define TSTRIDE (BK * ROWH * 2)          // bytes per tile-stage: 17408
#define BS_OFF  (3 * TSTRIDE)            // B tiles after 3 A stages: 52224
#define AUX_OFF (6 * TSTRIDE)            // 104448
#define GEMM_SMEM (AUX_OFF + 4 * 128 * 4)  // + attR/attQ/srow/scol = 106496

__global__ void __launch_bounds__(128) gemm_kernel() {
    extern __shared__ char sm[];
    float* attR = (float*)(sm + AUX_OFF);
    float* attQ = attR + 128;
    float* srow = attQ + 128;
    float* scol = srow + 128;

    int b    = blockIdx.y;
    int pair = blockIdx.x;
    int i = 0, rem = pair;
    while (rem >= NT - i) { rem -= NT - i; i++; }
    int j = i + rem;
    int rblk = i * 128;
    int qblk = j * 128;
    bool diag = (i == j);

    int tid  = threadIdx.x;
    int lane = tid & 31;
    int wid  = tid >> 5;          // 0..3
    int warpR = (wid >> 1) * 64;  // 2 warp-rows of 64
    int warpQ = (wid & 1) * 64;   // 2 warp-cols of 64

    attR[tid] = g_att[b * NN + rblk + tid];
    attQ[tid] = g_att[b * NN + qblk + tid];
    srow[tid] = 0.f; scol[tid] = 0.f;

    const __half* xb = g_xn + (size_t)b * CC * NN;
    uint32_t as_base = smem_u32(sm);
    uint32_t bs_base = as_base + BS_OFF;

    // stage load: 2 tiles x 64 k-rows x 16 granules(16B) = 2048 granules, 16/thread
    auto load_stage = [&](int round, int stg) {
        int kof = round * BK;
        #pragma unroll
        for (int it = 0; it < 16; it++) {
            int g = tid + it * 128;
            int tsel = g >> 10;           // 0 = A, 1 = B
            int r    = (g >> 4) & 63;     // k row
            int c16  = g & 15;            // 16B granule (8 halves)
            const __half* src = xb + (size_t)(kof + r) * NN +
                                (tsel ? qblk : rblk) + c16 * 8;
            uint32_t dst = (tsel ? bs_base : as_base) +
                           (uint32_t)stg * TSTRIDE + r * (ROWH * 2) + c16 * 16;
            cp_async16(dst, src);
        }
        CP_COMMIT();
    };

    float acc[4][8][4];
    #pragma unroll
    for (int mi = 0; mi < 4; mi++)
        #pragma unroll
        for (int ni = 0; ni < 8; ni++)
            #pragma unroll
            for (int k = 0; k < 4; k++) acc[mi][ni][k] = 0.f;

    // per-lane ldmatrix address components
    int l8 = lane & 7;
    int a_k = l8 + ((lane >> 4) & 1) * 8;
    int a_m = ((lane >> 3) & 1) * 8;
    int b_k = l8 + ((lane >> 3) & 1) * 8;
    int b_n = ((lane >> 4) & 1) * 8;

    uint32_t a_off[4], b_off[4];
    #pragma unroll
    for (int mi = 0; mi < 4; mi++)
        a_off[mi] = (uint32_t)(a_k * ROWH + warpR + mi * 16 + a_m) * 2;
    #pragma unroll
    for (int q = 0; q < 4; q++)
        b_off[q] = (uint32_t)(b_k * ROWH + warpQ + q * 16 + b_n) * 2;

    load_stage(0, 0);
    load_stage(1, 1);

    const int ROUNDS = CC / BK;   // 8
    int tg = lane & 3;
    int gp = lane >> 2;

    for (int kb = 0; kb < ROUNDS; kb++) {
        int cs = kb % 3;
        if (kb < ROUNDS - 1) asm volatile("cp.async.wait_group 1;" ::: "memory");
        else                 asm volatile("cp.async.wait_group 0;" ::: "memory");
        __syncthreads();

        if (kb + 2 < ROUNDS) load_stage(kb + 2, (kb + 2) % 3);

        uint32_t stage_a = as_base + (uint32_t)cs * TSTRIDE;
        uint32_t stage_b = bs_base + (uint32_t)cs * TSTRIDE;

        #pragma unroll
        for (int ks = 0; ks < BK; ks += 16) {
            uint32_t krow = (uint32_t)ks * (ROWH * 2);
            uint32_t afr[4][4], bfr[8][2];
            #pragma unroll
            for (int mi = 0; mi < 4; mi++)
                LDSM_X4_T(afr[mi][0], afr[mi][1], afr[mi][2], afr[mi][3],
                          stage_a + krow + a_off[mi]);
            #pragma unroll
            for (int q = 0; q < 4; q++)
                LDSM_X4_T(bfr[2 * q][0], bfr[2 * q][1], bfr[2 * q + 1][0], bfr[2 * q + 1][1],
                          stage_b + krow + b_off[q]);
            #pragma unroll
            for (int mi = 0; mi < 4; mi++)
                #pragma unroll
                for (int ni = 0; ni < 8; ni++)
                    mma_f16(acc[mi][ni], afr[mi], bfr[ni]);
        }
    }
    __syncthreads();

    // ----- epilogue -----
    float csum[8][2];
    #pragma unroll
    for (int ni = 0; ni < 8; ni++) { csum[ni][0] = 0.f; csum[ni][1] = 0.f; }

    #pragma unroll
    for (int mi = 0; mi < 4; mi++) {
        int r0 = warpR + mi * 16 + gp;
        int r1 = r0 + 8;
        float ar0 = attR[r0], ar1 = attR[r1];
        float rlo = 0.f, rhi = 0.f;
        #pragma unroll
        for (int ni = 0; ni < 8; ni++) {
            int c0 = warpQ + ni * 8 + tg * 2;
            int c1 = c0 + 1;
            float aq0 = attQ[c0], aq1 = attQ[c1];
            float s, p;
            s = fmaxf(acc[mi][ni][0], 0.f); p = s * s;
            rlo = fmaf(p, aq0, rlo); csum[ni][0] = fmaf(p, ar0, csum[ni][0]);
            s = fmaxf(acc[mi][ni][1], 0.f); p = s * s;
            rlo = fmaf(p, aq1, rlo); csum[ni][1] = fmaf(p, ar0, csum[ni][1]);
            s = fmaxf(acc[mi][ni][2], 0.f); p = s * s;
            rhi = fmaf(p, aq0, rhi); csum[ni][0] = fmaf(p, ar1, csum[ni][0]);
            s = fmaxf(acc[mi][ni][3], 0.f); p = s * s;
            rhi = fmaf(p, aq1, rhi); csum[ni][1] = fmaf(p, ar1, csum[ni][1]);
        }
        rlo += __shfl_xor_sync(0xffffffffu, rlo, 1);
        rlo += __shfl_xor_sync(0xffffffffu, rlo, 2);
        rhi += __shfl_xor_sync(0xffffffffu, rhi, 1);
        rhi += __shfl_xor_sync(0xffffffffu, rhi, 2);
        if (tg == 0) {
            atomicAdd(&srow[r0], rlo);
            atomicAdd(&srow[r1], rhi);
        }
    }
    if (!diag) {
        #pragma unroll
        for (int ni = 0; ni < 8; ni++) {
            float c0v = csum[ni][0], c1v = csum[ni][1];
            c0v += __shfl_xor_sync(0xffffffffu, c0v, 4);
            c0v += __shfl_xor_sync(0xffffffffu, c0v, 8);
            c0v += __shfl_xor_sync(0xffffffffu, c0v, 16);
            c1v += __shfl_xor_sync(0xffffffffu, c1v, 4);
            c1v += __shfl_xor_sync(0xffffffffu, c1v, 8);
            c1v += __shfl_xor_sync(0xffffffffu, c1v, 16);
            if (gp == 0) {
                int c0 = warpQ + ni * 8 + tg * 2;
                atomicAdd(&scol[c0],     c0v);
                atomicAdd(&scol[c0 + 1], c1v);
            }
        }
    }
    __syncthreads();

    atomicAdd(&g_refine[b * NN + rblk + tid], srow[tid]);
    if (!diag) atomicAdd(&g_refine[b * NN + qblk + tid], scol[tid]);
}

// ---------------------------------------------------------------------------
// out: warp per (b,c): out[b][c] = mean_n x[b][c][n] * refine[b][n]
// grid = BB*CC/8 = 1024, block 256 (8 warps)
// ---------------------------------------------------------------------------
__global__ void __launch_bounds__(256) out_kernel(const float* __restrict__ x,
                                                  float* __restrict__ out) {
    int wid  = threadIdx.x >> 5;
    int lane = threadIdx.x & 31;
    int bc = blockIdx.x * 8 + wid;
    int b = bc >> 9;

    const float4* xr = (const float4*)(x + (size_t)bc * NN);
    const float4* rf = (const float4*)(g_refine + b * NN);

    float s = 0.f;
    #pragma unroll 6
    for (int k = 0; k < 18; k++) {
        int q = lane + k * 32;
        float4 xv = __ldg(&xr[q]);
        float4 rv = rf[q];
        s = fmaf(xv.x, rv.x, s);
        s = fmaf(xv.y, rv.y, s);
        s = fmaf(xv.z, rv.z, s);
        s = fmaf(xv.w, rv.w, s);
    }
    #pragma unroll
    for (int off = 16; off > 0; off >>= 1)
        s += __shfl_xor_sync(0xffffffffu, s, off);
    if (lane == 0) out[bc] = s * (1.0f / (float)NN);
}

// ---------------------------------------------------------------------------
extern "C" void kernel_launch(void* const* d_in, const int* in_sizes, int n_in,
                              void* d_out, int out_size) {
    const float* x  = (const float*)d_in[0];   // [16, 512, 48, 48]
    const float* wq = (const float*)d_in[1];   // [512]
    float* out = (float*)d_out;                // [16, 512, 1, 1]

    cudaFuncSetAttribute(gemm_kernel, cudaFuncAttributeMaxDynamicSharedMemorySize, GEMM_SMEM);

    prep_kernel<<<BB * (NN / 32), 256>>>(x, wq);
    gemm_kernel<<<dim3(NPAIRS, BB), 128, GEMM_SMEM>>>();
    out_kernel<<<(BB * CC) / 8, 256>>>(x, out);
}

// round 13
// speedup vs baseline: 1.0677x; 1.0677x over previous
#include <cuda_runtime.h>
#include <cuda_fp16.h>
#include <math.h>
#include <stdint.h>

#define BB 16
#define CC 512
#define NN 2304
#define NT 18            // NN / 128 tiles
#define NPAIRS 171       // NT*(NT+1)/2

// ---------------- scratch (__device__ globals; no allocs allowed) -----------
__device__ __half g_xn[(size_t)BB * CC * NN];   // fp16-RN normalized x, [b][c][n]
__device__ float g_att[BB * NN];
__device__ float g_nrm[BB * NN];                // ||x||_n (clamped)
__device__ float g_refine[BB * NN];

__device__ __forceinline__ uint32_t smem_u32(const void* p) {
    uint32_t a;
    asm("{ .reg .u64 t; cvta.to.shared.u64 t, %1; cvt.u32.u64 %0, t; }" : "=r"(a) : "l"(p));
    return a;
}
__device__ __forceinline__ void cp_async16(uint32_t dst, const void* src) {
    asm volatile("cp.async.cg.shared.global [%0], [%1], 16;" :: "r"(dst), "l"(src) : "memory");
}
#define CP_COMMIT() asm volatile("cp.async.commit_group;" ::: "memory")

__device__ __forceinline__ void mma_f16(float c[4], const uint32_t a[4], const uint32_t b[2]) {
    asm("mma.sync.aligned.m16n8k16.row.col.f32.f16.f16.f32 "
        "{%0,%1,%2,%3}, {%4,%5,%6,%7}, {%8,%9}, {%0,%1,%2,%3};"
        : "+f"(c[0]), "+f"(c[1]), "+f"(c[2]), "+f"(c[3])
        : "r"(a[0]), "r"(a[1]), "r"(a[2]), "r"(a[3]), "r"(b[0]), "r"(b[1]));
}

#define LDSM_X4_T(r0, r1, r2, r3, addr) \
    asm volatile("ldmatrix.sync.aligned.m8n8.x4.trans.shared.b16 {%0,%1,%2,%3}, [%4];" \
        : "=r"(r0), "=r"(r1), "=r"(r2), "=r"(r3) : "r"(addr))

// ---------------------------------------------------------------------------
// prep: block = 32 n x 8 c-slices (64 c each). Phase1 ss/dot -> inv, att, nrm;
// phase2 cache-hot re-read writes g_xn fp16. grid = BB * NN/32 = 1152
// ---------------------------------------------------------------------------
__global__ void __launch_bounds__(256) prep_kernel(const float* __restrict__ x,
                                                   const float* __restrict__ wq) {
    __shared__ float swq[CC];
    __shared__ float s_ss[256], s_dot[256];
    __shared__ float s_inv[32];

    int tid = threadIdx.x;
    for (int i = tid; i < CC; i += 256) swq[i] = wq[i];
    __syncthreads();

    int b  = blockIdx.x / (NN / 32);
    int nt = blockIdx.x % (NN / 32);
    int cs = tid >> 5;          // c-slice 0..7 (64 c each)
    int nl = tid & 31;
    int n  = nt * 32 + nl;

    const float* xb = x + ((size_t)b * CC + cs * 64) * NN + n;
    const float* wp = swq + cs * 64;

    float ss = 0.f, dot = 0.f;
    #pragma unroll 16
    for (int c = 0; c < 64; c++) {
        float v = xb[(size_t)c * NN];
        ss  = fmaf(v, v, ss);
        dot = fmaf(v, wp[c], dot);
    }
    s_ss[tid] = ss; s_dot[tid] = dot;
    __syncthreads();

    if (tid < 32) {
        float tss = 0.f, td = 0.f;
        #pragma unroll
        for (int k = 0; k < 8; k++) {
            tss += s_ss[tid + 32 * k];
            td  += s_dot[tid + 32 * k];
        }
        float nrm = fmaxf(sqrtf(tss), 1e-12f);
        s_inv[tid] = 1.0f / nrm;
        int gid = b * NN + nt * 32 + tid;
        g_nrm[gid]    = nrm;
        g_att[gid]    = (td > 20.0f) ? td : log1pf(expf(td));
        g_refine[gid] = 0.0f;
    }
    __syncthreads();

    float inv = s_inv[nl];
    __half* ob = g_xn + ((size_t)b * CC + cs * 64) * NN + n;
    #pragma unroll 16
    for (int c = 0; c < 64; c++) {
        float v = xb[(size_t)c * NN];
        ob[(size_t)c * NN] = __float2half_rn(v * inv);
    }
}

// ---------------------------------------------------------------------------
// gemm (R11 config): per (b, tile-pair i<=j): S = Xn_i^T Xn_j over K=512.
// 128x128 CTA tile, 8 warps of 32x64. smem [k][n] stride 136 halves;
// ldmatrix.x4.trans fragments. BK=64, 3-stage cp.async, one sync per round.
// ---------------------------------------------------------------------------
#define BK 64
#define ROWH 136                         // halves per smem row (128 + 8 pad)
#define TSTRIDE (BK * ROWH * 2)          // bytes per tile-stage: 17408
#define BS_OFF  (3 * TSTRIDE)            // B tiles after 3 A stages: 52224
#define AUX_OFF (6 * TSTRIDE)            // 104448
#define GEMM_SMEM (AUX_OFF + 4 * 128 * 4)  // + attR/attQ/srow/scol = 106496

__global__ void __launch_bounds__(256) gemm_kernel() {
    extern __shared__ char sm[];
    float* attR = (float*)(sm + AUX_OFF);
    float* attQ = attR + 128;
    float* srow = attQ + 128;
    float* scol = srow + 128;

    int b    = blockIdx.y;
    int pair = blockIdx.x;
    int i = 0, rem = pair;
    while (rem >= NT - i) { rem -= NT - i; i++; }
    int j = i + rem;
    int rblk = i * 128;
    int qblk = j * 128;
    bool diag = (i == j);

    int tid  = threadIdx.x;
    int lane = tid & 31;
    int wid  = tid >> 5;
    int warpR = (wid >> 1) * 32;  // 4 warp-rows
    int warpQ = (wid & 1) * 64;   // 2 warp-cols

    if (tid < 128) {
        attR[tid] = g_att[b * NN + rblk + tid];
        attQ[tid] = g_att[b * NN + qblk + tid];
        srow[tid] = 0.f; scol[tid] = 0.f;
    }

    const __half* xb = g_xn + (size_t)b * CC * NN;
    uint32_t as_base = smem_u32(sm);
    uint32_t bs_base = as_base + BS_OFF;

    // stage load: 2 tiles x 64 k-rows x 16 granules(16B) = 2048 granules, 8/thread
    auto load_stage = [&](int round, int stg) {
        int kof = round * BK;
        #pragma unroll
        for (int it = 0; it < 8; it++) {
            int g = tid + it * 256;
            int tsel = g >> 10;           // 0 = A, 1 = B
            int r    = (g >> 4) & 63;     // k row
            int c16  = g & 15;            // 16B granule (8 halves)
            const __half* src = xb + (size_t)(kof + r) * NN +
                                (tsel ? qblk : rblk) + c16 * 8;
            uint32_t dst = (tsel ? bs_base : as_base) +
                           (uint32_t)stg * TSTRIDE + r * (ROWH * 2) + c16 * 16;
            cp_async16(dst, src);
        }
        CP_COMMIT();
    };

    float acc[2][8][4];
    #pragma unroll
    for (int mi = 0; mi < 2; mi++)
        #pragma unroll
        for (int ni = 0; ni < 8; ni++)
            #pragma unroll
            for (int k = 0; k < 4; k++) acc[mi][ni][k] = 0.f;

    // per-lane ldmatrix address components
    int l8 = lane & 7;
    int a_k = l8 + ((lane >> 4) & 1) * 8;
    int a_m = ((lane >> 3) & 1) * 8;
    int b_k = l8 + ((lane >> 3) & 1) * 8;
    int b_n = ((lane >> 4) & 1) * 8;

    uint32_t a_off0 = (uint32_t)(a_k * ROWH + warpR + a_m) * 2;
    uint32_t a_off1 = a_off0 + 16 * 2;
    uint32_t b_off[4];
    #pragma unroll
    for (int q = 0; q < 4; q++)
        b_off[q] = (uint32_t)(b_k * ROWH + warpQ + q * 16 + b_n) * 2;

    load_stage(0, 0);
    load_stage(1, 1);

    const int ROUNDS = CC / BK;   // 8
    int tg = lane & 3;
    int gp = lane >> 2;

    for (int kb = 0; kb < ROUNDS; kb++) {
        int cs = kb % 3;
        if (kb < ROUNDS - 1) asm volatile("cp.async.wait_group 1;" ::: "memory");
        else                 asm volatile("cp.async.wait_group 0;" ::: "memory");
        __syncthreads();

        if (kb + 2 < ROUNDS) load_stage(kb + 2, (kb + 2) % 3);

        uint32_t stage_a = as_base + (uint32_t)cs * TSTRIDE;
        uint32_t stage_b = bs_base + (uint32_t)cs * TSTRIDE;

        #pragma unroll
        for (int ks = 0; ks < BK; ks += 16) {
            uint32_t krow = (uint32_t)ks * (ROWH * 2);
            uint32_t afr[2][4], bfr[8][2];
            LDSM_X4_T(afr[0][0], afr[0][1], afr[0][2], afr[0][3], stage_a + krow + a_off0);
            LDSM_X4_T(afr[1][0], afr[1][1], afr[1][2], afr[1][3], stage_a + krow + a_off1);
            #pragma unroll
            for (int q = 0; q < 4; q++)
                LDSM_X4_T(bfr[2 * q][0], bfr[2 * q][1], bfr[2 * q + 1][0], bfr[2 * q + 1][1],
                          stage_b + krow + b_off[q]);
            #pragma unroll
            for (int mi = 0; mi < 2; mi++)
                #pragma unroll
                for (int ni = 0; ni < 8; ni++)
                    mma_f16(acc[mi][ni], afr[mi], bfr[ni]);
        }
    }
    __syncthreads();

    // ----- epilogue -----
    float csum[8][2];
    #pragma unroll
    for (int ni = 0; ni < 8; ni++) { csum[ni][0] = 0.f; csum[ni][1] = 0.f; }

    #pragma unroll
    for (int mi = 0; mi < 2; mi++) {
        int r0 = warpR + mi * 16 + gp;
        int r1 = r0 + 8;
        float ar0 = attR[r0], ar1 = attR[r1];
        float rlo = 0.f, rhi = 0.f;
        #pragma unroll
        for (int ni = 0; ni < 8; ni++) {
            int c0 = warpQ + ni * 8 + tg * 2;
            int c1 = c0 + 1;
            float aq0 = attQ[c0], aq1 = attQ[c1];
            float s, p;
            s = fmaxf(acc[mi][ni][0], 0.f); p = s * s;
            rlo = fmaf(p, aq0, rlo); csum[ni][0] = fmaf(p, ar0, csum[ni][0]);
            s = fmaxf(acc[mi][ni][1], 0.f); p = s * s;
            rlo = fmaf(p, aq1, rlo); csum[ni][1] = fmaf(p, ar0, csum[ni][1]);
            s = fmaxf(acc[mi][ni][2], 0.f); p = s * s;
            rhi = fmaf(p, aq0, rhi); csum[ni][0] = fmaf(p, ar1, csum[ni][0]);
            s = fmaxf(acc[mi][ni][3], 0.f); p = s * s;
            rhi = fmaf(p, aq1, rhi); csum[ni][1] = fmaf(p, ar1, csum[ni][1]);
        }
        rlo += __shfl_xor_sync(0xffffffffu, rlo, 1);
        rlo += __shfl_xor_sync(0xffffffffu, rlo, 2);
        rhi += __shfl_xor_sync(0xffffffffu, rhi, 1);
        rhi += __shfl_xor_sync(0xffffffffu, rhi, 2);
        if (tg == 0) {
            atomicAdd(&srow[r0], rlo);
            atomicAdd(&srow[r1], rhi);
        }
    }
    if (!diag) {
        #pragma unroll
        for (int ni = 0; ni < 8; ni++) {
            float c0v = csum[ni][0], c1v = csum[ni][1];
            c0v += __shfl_xor_sync(0xffffffffu, c0v, 4);
            c0v += __shfl_xor_sync(0xffffffffu, c0v, 8);
            c0v += __shfl_xor_sync(0xffffffffu, c0v, 16);
            c1v += __shfl_xor_sync(0xffffffffu, c1v, 4);
            c1v += __shfl_xor_sync(0xffffffffu, c1v, 8);
            c1v += __shfl_xor_sync(0xffffffffu, c1v, 16);
            if (gp == 0) {
                int c0 = warpQ + ni * 8 + tg * 2;
                atomicAdd(&scol[c0],     c0v);
                atomicAdd(&scol[c0 + 1], c1v);
            }
        }
    }
    __syncthreads();

    if (tid < 128) {
        atomicAdd(&g_refine[b * NN + rblk + tid], srow[tid]);
        if (!diag) atomicAdd(&g_refine[b * NN + qblk + tid], scol[tid]);
    }
}

// ---------------------------------------------------------------------------
// out: warp per (b,c): out[b][c] = mean_n xn_fp16[b][c][n] * (nrm[n]*refine[n])
// reads fp16 scratch (75.5 MB) instead of fp32 x (151 MB).
// grid = BB*CC/8 = 1024, block 256 (8 warps)
// ---------------------------------------------------------------------------
__global__ void __launch_bounds__(256) out_kernel(float* __restrict__ out) {
    int wid  = threadIdx.x >> 5;
    int lane = threadIdx.x & 31;
    int bc = blockIdx.x * 8 + wid;
    int b = bc >> 9;

    const uint4*  xr = (const uint4*)(g_xn + (size_t)bc * NN);   // 288 granules of 8 halves
    const float4* rf = (const float4*)(g_refine + b * NN);
    const float4* nf = (const float4*)(g_nrm + b * NN);

    float s = 0.f;
    #pragma unroll 3
    for (int k = 0; k < 9; k++) {
        int q = lane + k * 32;               // granule index, n = q*8..q*8+7
        uint4 h = __ldg(&xr[q]);
        float4 r0 = rf[2 * q],     n0 = nf[2 * q];
        float4 r1 = rf[2 * q + 1], n1 = nf[2 * q + 1];
        float2 f;
        f = __half22float2(*(const __half2*)&h.x);
        s = fmaf(f.x, r0.x * n0.x, s); s = fmaf(f.y, r0.y * n0.y, s);
        f = __half22float2(*(const __half2*)&h.y);
        s = fmaf(f.x, r0.z * n0.z, s); s = fmaf(f.y, r0.w * n0.w, s);
        f = __half22float2(*(const __half2*)&h.z);
        s = fmaf(f.x, r1.x * n1.x, s); s = fmaf(f.y, r1.y * n1.y, s);
        f = __half22float2(*(const __half2*)&h.w);
        s = fmaf(f.x, r1.z * n1.z, s); s = fmaf(f.y, r1.w * n1.w, s);
    }
    #pragma unroll
    for (int off = 16; off > 0; off >>= 1)
        s += __shfl_xor_sync(0xffffffffu, s, off);
    if (lane == 0) out[bc] = s * (1.0f / (float)NN);
}

// ---------------------------------------------------------------------------
extern "C" void kernel_launch(void* const* d_in, const int* in_sizes, int n_in,
                              void* d_out, int out_size) {
    const float* x  = (const float*)d_in[0];   // [16, 512, 48, 48]
    const float* wq = (const float*)d_in[1];   // [512]
    float* out = (float*)d_out;                // [16, 512, 1, 1]

    cudaFuncSetAttribute(gemm_kernel, cudaFuncAttributeMaxDynamicSharedMemorySize, GEMM_SMEM);

    prep_kernel<<<BB * (NN / 32), 256>>>(x, wq);
    gemm_kernel<<<dim3(NPAIRS, BB), 256, GEMM_SMEM>>>();
    out_kernel<<<(BB * CC) / 8, 256>>>(out);
}

// round 14
// speedup vs baseline: 1.0948x; 1.0254x over previous
#include <cuda_runtime.h>
#include <cuda_fp16.h>
#include <math.h>
#include <stdint.h>

#define BB 16
#define CC 512
#define NN 2304
#define NT 18            // NN / 128 tiles
#define NPAIRS 171       // NT*(NT+1)/2

// ---------------- scratch (__device__ globals; no allocs allowed) -----------
__device__ __half g_xn[(size_t)BB * CC * NN];   // fp16-RN normalized x, [b][c][n]
__device__ float g_att[BB * NN];
__device__ float g_nrm[BB * NN];                // ||x||_n (clamped)
__device__ float g_refine[BB * NN];

__device__ __forceinline__ uint32_t smem_u32(const void* p) {
    uint32_t a;
    asm("{ .reg .u64 t; cvta.to.shared.u64 t, %1; cvt.u32.u64 %0, t; }" : "=r"(a) : "l"(p));
    return a;
}
__device__ __forceinline__ void cp_async16(uint32_t dst, const void* src) {
    asm volatile("cp.async.cg.shared.global [%0], [%1], 16;" :: "r"(dst), "l"(src) : "memory");
}
#define CP_COMMIT() asm volatile("cp.async.commit_group;" ::: "memory")

__device__ __forceinline__ void mma_f16(float c[4], const uint32_t a[4], const uint32_t b[2]) {
    asm("mma.sync.aligned.m16n8k16.row.col.f32.f16.f16.f32 "
        "{%0,%1,%2,%3}, {%4,%5,%6,%7}, {%8,%9}, {%0,%1,%2,%3};"
        : "+f"(c[0]), "+f"(c[1]), "+f"(c[2]), "+f"(c[3])
        : "r"(a[0]), "r"(a[1]), "r"(a[2]), "r"(a[3]), "r"(b[0]), "r"(b[1]));
}

#define LDSM_X4_T(r0, r1, r2, r3, addr) \
    asm volatile("ldmatrix.sync.aligned.m8n8.x4.trans.shared.b16 {%0,%1,%2,%3}, [%4];" \
        : "=r"(r0), "=r"(r1), "=r"(r2), "=r"(r3) : "r"(addr))

// ---------------------------------------------------------------------------
// prep: block = 32 n x 8 c-slices (64 c each). Phase1 ss/dot -> inv, att, nrm;
// phase2 cache-hot re-read writes g_xn fp16. grid = BB * NN/32 = 1152
// ---------------------------------------------------------------------------
__global__ void __launch_bounds__(256) prep_kernel(const float* __restrict__ x,
                                                   const float* __restrict__ wq) {
    __shared__ float swq[CC];
    __shared__ float s_ss[256], s_dot[256];
    __shared__ float s_inv[32];

    int tid = threadIdx.x;
    for (int i = tid; i < CC; i += 256) swq[i] = wq[i];
    __syncthreads();

    int b  = blockIdx.x / (NN / 32);
    int nt = blockIdx.x % (NN / 32);
    int cs = tid >> 5;          // c-slice 0..7 (64 c each)
    int nl = tid & 31;
    int n  = nt * 32 + nl;

    const float* xb = x + ((size_t)b * CC + cs * 64) * NN + n;
    const float* wp = swq + cs * 64;

    float ss = 0.f, dot = 0.f;
    #pragma unroll 16
    for (int c = 0; c < 64; c++) {
        float v = xb[(size_t)c * NN];
        ss  = fmaf(v, v, ss);
        dot = fmaf(v, wp[c], dot);
    }
    s_ss[tid] = ss; s_dot[tid] = dot;
    __syncthreads();

    if (tid < 32) {
        float tss = 0.f, td = 0.f;
        #pragma unroll
        for (int k = 0; k < 8; k++) {
            tss += s_ss[tid + 32 * k];
            td  += s_dot[tid + 32 * k];
        }
        float nrm = fmaxf(sqrtf(tss), 1e-12f);
        s_inv[tid] = 1.0f / nrm;
        int gid = b * NN + nt * 32 + tid;
        g_nrm[gid]    = nrm;
        g_att[gid]    = (td > 20.0f) ? td : log1pf(expf(td));
        g_refine[gid] = 0.0f;
    }
    __syncthreads();

    float inv = s_inv[nl];
    __half* ob = g_xn + ((size_t)b * CC + cs * 64) * NN + n;
    #pragma unroll 16
    for (int c = 0; c < 64; c++) {
        float v = xb[(size_t)c * NN];
        ob[(size_t)c * NN] = __float2half_rn(v * inv);
    }
}

// ---------------------------------------------------------------------------
// gemm (R11 config): per (b, tile-pair i<=j): S = Xn_i^T Xn_j over K=512.
// 128x128 CTA tile, 8 warps of 32x64. smem [k][n] stride 136 halves;
// ldmatrix.x4.trans fragments. BK=64, 3-stage cp.async, one sync per round.
// ---------------------------------------------------------------------------
#define BK 64
#define ROWH 136                         // halves per smem row (128 + 8 pad)
#define TSTRIDE (BK * ROWH * 2)          // bytes per tile-stage: 17408
#define BS_OFF  (3 * TSTRIDE)            // B tiles after 3 A stages: 52224
#define AUX_OFF (6 * TSTRIDE)            // 104448
#define GEMM_SMEM (AUX_OFF + 4 * 128 * 4)  // + attR/attQ/srow/scol = 106496

__global__ void __launch_bounds__(256) gemm_kernel() {
    extern __shared__ char sm[];
    float* attR = (float*)(sm + AUX_OFF);
    float* attQ = attR + 128;
    float* srow = attQ + 128;
    float* scol = srow + 128;

    int b    = blockIdx.y;
    int pair = blockIdx.x;
    int i = 0, rem = pair;
    while (rem >= NT - i) { rem -= NT - i; i++; }
    int j = i + rem;
    int rblk = i * 128;
    int qblk = j * 128;
    bool diag = (i == j);

    int tid  = threadIdx.x;
    int lane = tid & 31;
    int wid  = tid >> 5;
    int warpR = (wid >> 1) * 32;  // 4 warp-rows
    int warpQ = (wid & 1) * 64;   // 2 warp-cols

    if (tid < 128) {
        attR[tid] = g_att[b * NN + rblk + tid];
        attQ[tid] = g_att[b * NN + qblk + tid];
        srow[tid] = 0.f; scol[tid] = 0.f;
    }

    const __half* xb = g_xn + (size_t)b * CC * NN;
    uint32_t as_base = smem_u32(sm);
    uint32_t bs_base = as_base + BS_OFF;

    // stage load: 2 tiles x 64 k-rows x 16 granules(16B) = 2048 granules, 8/thread
    auto load_stage = [&](int round, int stg) {
        int kof = round * BK;
        #pragma unroll
        for (int it = 0; it < 8; it++) {
            int g = tid + it * 256;
            int tsel = g >> 10;           // 0 = A, 1 = B
            int r    = (g >> 4) & 63;     // k row
            int c16  = g & 15;            // 16B granule (8 halves)
            const __half* src = xb + (size_t)(kof + r) * NN +
                                (tsel ? qblk : rblk) + c16 * 8;
            uint32_t dst = (tsel ? bs_base : as_base) +
                           (uint32_t)stg * TSTRIDE + r * (ROWH * 2) + c16 * 16;
            cp_async16(dst, src);
        }
        CP_COMMIT();
    };

    float acc[2][8][4];
    #pragma unroll
    for (int mi = 0; mi < 2; mi++)
        #pragma unroll
        for (int ni = 0; ni < 8; ni++)
            #pragma unroll
            for (int k = 0; k < 4; k++) acc[mi][ni][k] = 0.f;

    // per-lane ldmatrix address components
    int l8 = lane & 7;
    int a_k = l8 + ((lane >> 4) & 1) * 8;
    int a_m = ((lane >> 3) & 1) * 8;
    int b_k = l8 + ((lane >> 3) & 1) * 8;
    int b_n = ((lane >> 4) & 1) * 8;

    uint32_t a_off0 = (uint32_t)(a_k * ROWH + warpR + a_m) * 2;
    uint32_t a_off1 = a_off0 + 16 * 2;
    uint32_t b_off[4];
    #pragma unroll
    for (int q = 0; q < 4; q++)
        b_off[q] = (uint32_t)(b_k * ROWH + warpQ + q * 16 + b_n) * 2;

    load_stage(0, 0);
    load_stage(1, 1);

    const int ROUNDS = CC / BK;   // 8
    int tg = lane & 3;
    int gp = lane >> 2;

    for (int kb = 0; kb < ROUNDS; kb++) {
        int cs = kb % 3;
        if (kb < ROUNDS - 1) asm volatile("cp.async.wait_group 1;" ::: "memory");
        else                 asm volatile("cp.async.wait_group 0;" ::: "memory");
        __syncthreads();

        if (kb + 2 < ROUNDS) load_stage(kb + 2, (kb + 2) % 3);

        uint32_t stage_a = as_base + (uint32_t)cs * TSTRIDE;
        uint32_t stage_b = bs_base + (uint32_t)cs * TSTRIDE;

        #pragma unroll
        for (int ks = 0; ks < BK; ks += 16) {
            uint32_t krow = (uint32_t)ks * (ROWH * 2);
            uint32_t afr[2][4], bfr[8][2];
            LDSM_X4_T(afr[0][0], afr[0][1], afr[0][2], afr[0][3], stage_a + krow + a_off0);
            LDSM_X4_T(afr[1][0], afr[1][1], afr[1][2], afr[1][3], stage_a + krow + a_off1);
            #pragma unroll
            for (int q = 0; q < 4; q++)
                LDSM_X4_T(bfr[2 * q][0], bfr[2 * q][1], bfr[2 * q + 1][0], bfr[2 * q + 1][1],
                          stage_b + krow + b_off[q]);
            #pragma unroll
            for (int mi = 0; mi < 2; mi++)
                #pragma unroll
                for (int ni = 0; ni < 8; ni++)
                    mma_f16(acc[mi][ni], afr[mi], bfr[ni]);
        }
    }
    __syncthreads();

    // ----- epilogue -----
    float csum[8][2];
    #pragma unroll
    for (int ni = 0; ni < 8; ni++) { csum[ni][0] = 0.f; csum[ni][1] = 0.f; }

    #pragma unroll
    for (int mi = 0; mi < 2; mi++) {
        int r0 = warpR + mi * 16 + gp;
        int r1 = r0 + 8;
        float ar0 = attR[r0], ar1 = attR[r1];
        float rlo = 0.f, rhi = 0.f;
        #pragma unroll
        for (int ni = 0; ni < 8; ni++) {
            int c0 = warpQ + ni * 8 + tg * 2;
            int c1 = c0 + 1;
            float aq0 = attQ[c0], aq1 = attQ[c1];
            float s, p;
            s = fmaxf(acc[mi][ni][0], 0.f); p = s * s;
            rlo = fmaf(p, aq0, rlo); csum[ni][0] = fmaf(p, ar0, csum[ni][0]);
            s = fmaxf(acc[mi][ni][1], 0.f); p = s * s;
            rlo = fmaf(p, aq1, rlo); csum[ni][1] = fmaf(p, ar0, csum[ni][1]);
            s = fmaxf(acc[mi][ni][2], 0.f); p = s * s;
            rhi = fmaf(p, aq0, rhi); csum[ni][0] = fmaf(p, ar1, csum[ni][0]);
            s = fmaxf(acc[mi][ni][3], 0.f); p = s * s;
            rhi = fmaf(p, aq1, rhi); csum[ni][1] = fmaf(p, ar1, csum[ni][1]);
        }
        rlo += __shfl_xor_sync(0xffffffffu, rlo, 1);
        rlo += __shfl_xor_sync(0xffffffffu, rlo, 2);
        rhi += __shfl_xor_sync(0xffffffffu, rhi, 1);
        rhi += __shfl_xor_sync(0xffffffffu, rhi, 2);
        if (tg == 0) {
            atomicAdd(&srow[r0], rlo);
            atomicAdd(&srow[r1], rhi);
        }
    }
    if (!diag) {
        #pragma unroll
        for (int ni = 0; ni < 8; ni++) {
            float c0v = csum[ni][0], c1v = csum[ni][1];
            c0v += __shfl_xor_sync(0xffffffffu, c0v, 4);
            c0v += __shfl_xor_sync(0xffffffffu, c0v, 8);
            c0v += __shfl_xor_sync(0xffffffffu, c0v, 16);
            c1v += __shfl_xor_sync(0xffffffffu, c1v, 4);
            c1v += __shfl_xor_sync(0xffffffffu, c1v, 8);
            c1v += __shfl_xor_sync(0xffffffffu, c1v, 16);
            if (gp == 0) {
                int c0 = warpQ + ni * 8 + tg * 2;
                atomicAdd(&scol[c0],     c0v);
                atomicAdd(&scol[c0 + 1], c1v);
            }
        }
    }
    __syncthreads();

    if (tid < 128) {
        atomicAdd(&g_refine[b * NN + rblk + tid], srow[tid]);
        if (!diag) atomicAdd(&g_refine[b * NN + qblk + tid], scol[tid]);
    }
}

// ---------------------------------------------------------------------------
// out: CTA = (b, 8 c-rows). Build w[n] = nrm*refine in smem ONCE, then each
// warp dots its fp16 x row against smem w. grid = BB*64 = 1024.
// ---------------------------------------------------------------------------
__global__ void __launch_bounds__(256) out_kernel(float* __restrict__ out) {
    __shared__ float w[NN];

    int tid  = threadIdx.x;
    int wid  = tid >> 5;
    int lane = tid & 31;
    int b  = blockIdx.x >> 6;
    int cg = blockIdx.x & 63;

    // build w: 2304 floats, 576 float4 ops over 256 threads
    const float4* rf = (const float4*)(g_refine + b * NN);
    const float4* nf = (const float4*)(g_nrm + b * NN);
    for (int q = tid; q < NN / 4; q += 256) {
        float4 r = rf[q], n = nf[q];
        float4 v; v.x = r.x * n.x; v.y = r.y * n.y; v.z = r.z * n.z; v.w = r.w * n.w;
        *(float4*)&w[q * 4] = v;
    }
    __syncthreads();

    int bc = (b << 9) + cg * 8 + wid;
    const uint4* xr = (const uint4*)(g_xn + (size_t)bc * NN);   // 288 granules of 8 halves

    float s = 0.f;
    #pragma unroll 3
    for (int k = 0; k < 9; k++) {
        int q = lane + k * 32;               // granule index, n = q*8..q*8+7
        uint4 h = __ldg(&xr[q]);
        const float* wp = w + q * 8;
        float2 f;
        f = __half22float2(*(const __half2*)&h.x);
        s = fmaf(f.x, wp[0], s); s = fmaf(f.y, wp[1], s);
        f = __half22float2(*(const __half2*)&h.y);
        s = fmaf(f.x, wp[2], s); s = fmaf(f.y, wp[3], s);
        f = __half22float2(*(const __half2*)&h.z);
        s = fmaf(f.x, wp[4], s); s = fmaf(f.y, wp[5], s);
        f = __half22float2(*(const __half2*)&h.w);
        s = fmaf(f.x, wp[6], s); s = fmaf(f.y, wp[7], s);
    }
    #pragma unroll
    for (int off = 16; off > 0; off >>= 1)
        s += __shfl_xor_sync(0xffffffffu, s, off);
    if (lane == 0) out[bc] = s * (1.0f / (float)NN);
}

// ---------------------------------------------------------------------------
extern "C" void kernel_launch(void* const* d_in, const int* in_sizes, int n_in,
                              void* d_out, int out_size) {
    const float* x  = (const float*)d_in[0];   // [16, 512, 48, 48]
    const float* wq = (const float*)d_in[1];   // [512]
    float* out = (float*)d_out;                // [16, 512, 1, 1]

    cudaFuncSetAttribute(gemm_kernel, cudaFuncAttributeMaxDynamicSharedMemorySize, GEMM_SMEM);

    prep_kernel<<<BB * (NN / 32), 256>>>(x, wq);
    gemm_kernel<<<dim3(NPAIRS, BB), 256, GEMM_SMEM>>>();
    out_kernel<<<BB * 64, 256>>>(out);
}